// round 2
// baseline (speedup 1.0000x reference)
#include <cuda_runtime.h>
#include <math.h>

#define B    4
#define C    64
#define H    128
#define W    128
#define COUT 64
#define KK   18       // 2*K offset channels
#define CK   576      // C*9
#define HW   16384    // H*W
#define TPX  16       // pixels per main-kernel block
#define SROW 580      // padded samp row (>=576, %4==0, %32!=0 banks)

// Scratch (device globals — no runtime allocation allowed)
__device__ float g_xt[B * HW * C];     // x transposed to [b][y][x][c]
__device__ float g_off[B * HW * KK];   // offsets [b][y][x][18]
__device__ float g_wkt[CK * COUT];     // weights [ck=c*9+k][o]

__device__ __forceinline__ void fma4(float4& a, float s, const float4& v) {
    a.x += s * v.x; a.y += s * v.y; a.z += s * v.z; a.w += s * v.w;
}

// ---------------------------------------------------------------------------
// Kernel 1: transpose x (B,C,H,W) -> (B,HW,C), SMEM-tiled 32x32
// ---------------------------------------------------------------------------
__global__ void k_transpose_x(const float* __restrict__ x) {
    __shared__ float tile[32][33];
    int b   = blockIdx.z;
    int c0  = blockIdx.y * 32;
    int hw0 = blockIdx.x * 32;
    int tx = threadIdx.x, ty = threadIdx.y;   // 32 x 8
#pragma unroll
    for (int j = 0; j < 4; j++) {
        int c = c0 + ty + j * 8;
        tile[ty + j * 8][tx] = x[(b * C + c) * HW + hw0 + tx];
    }
    __syncthreads();
#pragma unroll
    for (int j = 0; j < 4; j++) {
        int hw = hw0 + ty + j * 8;
        g_xt[(b * HW + hw) * C + c0 + tx] = tile[tx][ty + j * 8];
    }
}

// ---------------------------------------------------------------------------
// Kernel 2: transpose w_d (COUT, C, 3, 3) -> g_wkt[ck][o]
// ---------------------------------------------------------------------------
__global__ void k_wkt(const float* __restrict__ wd) {
    int i = blockIdx.x * 256 + threadIdx.x;
    if (i < CK * COUT) {
        int o = i / CK;
        int r = i % CK;                 // r = c*9 + k  (k = ky*3+kx)
        g_wkt[r * COUT + o] = wd[o * CK + r];
    }
}

// ---------------------------------------------------------------------------
// Kernel 3: offset conv — 3x3, C=64 -> 18, pad 1, + bias.
// One thread per pixel; w_p staged in SMEM as [c][tap][kk_padded20] for
// float4-vectorized accumulation over the 18 output channels.
// ---------------------------------------------------------------------------
__global__ void __launch_bounds__(256) k_offset(const float* __restrict__ x,
                                                const float* __restrict__ wp,
                                                const float* __restrict__ bp) {
    __shared__ float ws[C * 9 * 20];   // 46080 B
    int tid = threadIdx.x;
    for (int i = tid; i < C * 9 * 20; i += 256) {
        int kk = i % 20;
        int ct = i / 20;               // c*9 + tap
        ws[i] = (kk < 18) ? wp[kk * CK + ct] : 0.f;
    }
    __syncthreads();

    int pid = blockIdx.x * 256 + tid;
    int b  = pid >> 14;
    int yx = pid & (HW - 1);
    int y  = yx >> 7;
    int xx = yx & 127;

    float4 acc[5];
    {
        float a[20];
#pragma unroll
        for (int kk = 0; kk < 18; kk++) a[kk] = bp[kk];
        a[18] = 0.f; a[19] = 0.f;
#pragma unroll
        for (int q = 0; q < 5; q++)
            acc[q] = make_float4(a[4*q], a[4*q+1], a[4*q+2], a[4*q+3]);
    }

    const float* xb = x + b * C * HW;
    for (int c = 0; c < C; c++) {
        float v[9];
#pragma unroll
        for (int t = 0; t < 9; t++) {
            int yy = y + t / 3 - 1;
            int xc = xx + t % 3 - 1;
            bool ok = (yy >= 0 && yy < H && xc >= 0 && xc < W);
            v[t] = ok ? xb[c * HW + yy * W + xc] : 0.f;
        }
#pragma unroll
        for (int t = 0; t < 9; t++) {
            const float4* w4 = (const float4*)&ws[(c * 9 + t) * 20];
            float vv = v[t];
#pragma unroll
            for (int q = 0; q < 5; q++) {
                float4 wq = w4[q];
                acc[q].x += vv * wq.x;
                acc[q].y += vv * wq.y;
                acc[q].z += vv * wq.z;
                acc[q].w += vv * wq.w;
            }
        }
    }

    float a[20];
#pragma unroll
    for (int q = 0; q < 5; q++) {
        a[4*q] = acc[q].x; a[4*q+1] = acc[q].y;
        a[4*q+2] = acc[q].z; a[4*q+3] = acc[q].w;
    }
    float* op = g_off + (long)pid * KK;
#pragma unroll
    for (int kk = 0; kk < 18; kk++) op[kk] = a[kk];
}

// ---------------------------------------------------------------------------
// Kernel 4: main — bilinear sampling into SMEM samp[t][ck], then the
// (16 px) x (576 ck) x (64 o) GEMM with 4o x 2t x 4ck register tiling.
// 128 threads/block, 16 pixels of one row per block.
// ---------------------------------------------------------------------------
__global__ void __launch_bounds__(128) k_main(float* __restrict__ out) {
    __shared__ float smem[TPX * SROW];   // 37120 B; reused as [COUT][17] for output
    int b   = blockIdx.z;
    int y   = blockIdx.y;
    int x0  = blockIdx.x * TPX;
    int tid = threadIdx.x;

    // ---- Stage A: sampling. thread -> (pixel t, 8 channels)
    {
        int t  = tid >> 3;            // 0..15
        int c0 = (tid & 7) * 8;       // 0,8,...,56
        int xo = x0 + t;
        int pidx = b * HW + y * W + xo;
        const float* op = g_off + (long)pidx * KK;
        float* srow = smem + t * SROW;
#pragma unroll
        for (int k = 0; k < 9; k++) {
            int ky = k / 3, kx = k % 3;
            float py = op[2*k]     + (float)(y  + ky - 1);
            float px = op[2*k + 1] + (float)(xo + kx - 1);
            float fy = floorf(py), fx = floorf(px);
            float wy = py - fy,    wx = px - fx;
            int iy0 = (int)fy, ix0 = (int)fx;
            int iy1 = iy0 + 1, ix1 = ix0 + 1;
            float vy0 = (iy0 >= 0 && iy0 < H) ? 1.f : 0.f;
            float vy1 = (iy1 >= 0 && iy1 < H) ? 1.f : 0.f;
            float vx0 = (ix0 >= 0 && ix0 < W) ? 1.f : 0.f;
            float vx1 = (ix1 >= 0 && ix1 < W) ? 1.f : 0.f;
            float w00 = (1.f - wy) * (1.f - wx) * vy0 * vx0;
            float w01 = (1.f - wy) * wx         * vy0 * vx1;
            float w10 = wy         * (1.f - wx) * vy1 * vx0;
            float w11 = wy         * wx         * vy1 * vx1;
            int cy0 = min(max(iy0, 0), H - 1), cy1 = min(max(iy1, 0), H - 1);
            int cx0 = min(max(ix0, 0), W - 1), cx1 = min(max(ix1, 0), W - 1);
            const float* p00 = g_xt + ((long)(b * HW + cy0 * W + cx0)) * C + c0;
            const float* p01 = g_xt + ((long)(b * HW + cy0 * W + cx1)) * C + c0;
            const float* p10 = g_xt + ((long)(b * HW + cy1 * W + cx0)) * C + c0;
            const float* p11 = g_xt + ((long)(b * HW + cy1 * W + cx1)) * C + c0;
#pragma unroll
            for (int j = 0; j < 2; j++) {
                float4 a00 = *(const float4*)(p00 + 4*j);
                float4 a01 = *(const float4*)(p01 + 4*j);
                float4 a10 = *(const float4*)(p10 + 4*j);
                float4 a11 = *(const float4*)(p11 + 4*j);
                float s0 = w00*a00.x + w01*a01.x + w10*a10.x + w11*a11.x;
                float s1 = w00*a00.y + w01*a01.y + w10*a10.y + w11*a11.y;
                float s2 = w00*a00.z + w01*a01.z + w10*a10.z + w11*a11.z;
                float s3 = w00*a00.w + w01*a01.w + w10*a10.w + w11*a11.w;
                int cb = c0 + 4*j;
                srow[(cb + 0) * 9 + k] = s0;
                srow[(cb + 1) * 9 + k] = s1;
                srow[(cb + 2) * 9 + k] = s2;
                srow[(cb + 3) * 9 + k] = s3;
            }
        }
    }
    __syncthreads();

    // ---- Stage B: GEMM. thread -> 4 outputs (o0..o0+3) x 2 pixels (t0,t0+1)
    int o0 = (tid & 15) * 4;
    int t0 = (tid >> 4) * 2;
    float4 acc0 = make_float4(0,0,0,0);
    float4 acc1 = make_float4(0,0,0,0);
    {
        const float* s0p = smem + t0 * SROW;
        const float* s1p = smem + (t0 + 1) * SROW;
#pragma unroll 4
        for (int ckq = 0; ckq < 144; ckq++) {
            int ck = ckq * 4;
            float4 sa = *(const float4*)(s0p + ck);
            float4 sb = *(const float4*)(s1p + ck);
            float4 w0 = *(const float4*)&g_wkt[(ck + 0) * COUT + o0];
            float4 w1 = *(const float4*)&g_wkt[(ck + 1) * COUT + o0];
            float4 w2 = *(const float4*)&g_wkt[(ck + 2) * COUT + o0];
            float4 w3 = *(const float4*)&g_wkt[(ck + 3) * COUT + o0];
            fma4(acc0, sa.x, w0); fma4(acc0, sa.y, w1);
            fma4(acc0, sa.z, w2); fma4(acc0, sa.w, w3);
            fma4(acc1, sb.x, w0); fma4(acc1, sb.y, w1);
            fma4(acc1, sb.z, w2); fma4(acc1, sb.w, w3);
        }
    }

    // ---- Output: stage through SMEM for coalesced global stores
    __syncthreads();
    float* ob = smem;                 // [COUT][17]
    ob[(o0 + 0) * 17 + t0] = acc0.x;
    ob[(o0 + 1) * 17 + t0] = acc0.y;
    ob[(o0 + 2) * 17 + t0] = acc0.z;
    ob[(o0 + 3) * 17 + t0] = acc0.w;
    ob[(o0 + 0) * 17 + t0 + 1] = acc1.x;
    ob[(o0 + 1) * 17 + t0 + 1] = acc1.y;
    ob[(o0 + 2) * 17 + t0 + 1] = acc1.z;
    ob[(o0 + 3) * 17 + t0 + 1] = acc1.w;
    __syncthreads();
    for (int i = tid; i < COUT * TPX; i += 128) {
        int o = i >> 4;
        int t = i & 15;
        out[((long)(b * COUT + o) * H + y) * W + x0 + t] = ob[o * 17 + t];
    }
}

// ---------------------------------------------------------------------------
extern "C" void kernel_launch(void* const* d_in, const int* in_sizes, int n_in,
                              void* d_out, int out_size) {
    const float* x  = (const float*)d_in[0];
    const float* wp = (const float*)d_in[1];
    const float* bp = (const float*)d_in[2];
    const float* wd = (const float*)d_in[3];
    float* out = (float*)d_out;

    k_transpose_x<<<dim3(HW / 32, C / 32, B), dim3(32, 8)>>>(x);
    k_wkt<<<(CK * COUT + 255) / 256, 256>>>(wd);
    k_offset<<<(B * HW) / 256, 256>>>(x, wp, bp);
    k_main<<<dim3(W / TPX, H, B), 128>>>(out);
}

// round 3
// speedup vs baseline: 1.0274x; 1.0274x over previous
#include <cuda_runtime.h>
#include <math.h>

#define B    4
#define C    64
#define H    128
#define W    128
#define COUT 64
#define KK   18       // 2*K offset channels
#define CK   576      // C*9
#define HW   16384    // H*W
#define TPX  32       // pixels per main-kernel block
#define SROW 580      // padded samp row (576 + 4; 580 % 32 == 4)

// Scratch (device globals — no runtime allocation allowed)
__device__ float g_xt[B * HW * C];       // x transposed to [b][y][x][c]
__device__ float g_off[B * HW * KK];     // offsets [b][y][x][18]
__device__ float g_wkt2[9 * C * COUT];   // weights [k][c][o]

__device__ __forceinline__ void fma4(float4& a, float s, const float4& v) {
    a.x += s * v.x; a.y += s * v.y; a.z += s * v.z; a.w += s * v.w;
}

// ---------------------------------------------------------------------------
// Kernel 1: transpose x (B,C,H,W) -> (B,HW,C), SMEM-tiled 32x32
// ---------------------------------------------------------------------------
__global__ void k_transpose_x(const float* __restrict__ x) {
    __shared__ float tile[32][33];
    int b   = blockIdx.z;
    int c0  = blockIdx.y * 32;
    int hw0 = blockIdx.x * 32;
    int tx = threadIdx.x, ty = threadIdx.y;   // 32 x 8
#pragma unroll
    for (int j = 0; j < 4; j++) {
        int c = c0 + ty + j * 8;
        tile[ty + j * 8][tx] = x[(b * C + c) * HW + hw0 + tx];
    }
    __syncthreads();
#pragma unroll
    for (int j = 0; j < 4; j++) {
        int hw = hw0 + ty + j * 8;
        g_xt[(b * HW + hw) * C + c0 + tx] = tile[tx][ty + j * 8];
    }
}

// ---------------------------------------------------------------------------
// Kernel 2: reorder w_d (COUT, C, 3, 3) -> g_wkt2[k][c][o]
// ---------------------------------------------------------------------------
__global__ void k_wkt(const float* __restrict__ wd) {
    int d = blockIdx.x * 256 + threadIdx.x;
    if (d < 9 * C * COUT) {
        int o = d & 63;
        int c = (d >> 6) & 63;
        int k = d >> 12;
        g_wkt2[d] = wd[o * CK + c * 9 + k];
    }
}

// ---------------------------------------------------------------------------
// Kernel 3: offset conv — 3x3, C=64 -> 18, pad 1, + bias.
// ---------------------------------------------------------------------------
__global__ void __launch_bounds__(256) k_offset(const float* __restrict__ x,
                                                const float* __restrict__ wp,
                                                const float* __restrict__ bp) {
    __shared__ float ws[C * 9 * 20];   // 46080 B
    int tid = threadIdx.x;
    for (int i = tid; i < C * 9 * 20; i += 256) {
        int kk = i % 20;
        int ct = i / 20;               // c*9 + tap
        ws[i] = (kk < 18) ? wp[kk * CK + ct] : 0.f;
    }
    __syncthreads();

    int pid = blockIdx.x * 256 + tid;
    int b  = pid >> 14;
    int yx = pid & (HW - 1);
    int y  = yx >> 7;
    int xx = yx & 127;

    float4 acc[5];
    {
        float a[20];
#pragma unroll
        for (int kk = 0; kk < 18; kk++) a[kk] = bp[kk];
        a[18] = 0.f; a[19] = 0.f;
#pragma unroll
        for (int q = 0; q < 5; q++)
            acc[q] = make_float4(a[4*q], a[4*q+1], a[4*q+2], a[4*q+3]);
    }

    const float* xb = x + b * C * HW;
    for (int c = 0; c < C; c++) {
        float v[9];
#pragma unroll
        for (int t = 0; t < 9; t++) {
            int yy = y + t / 3 - 1;
            int xc = xx + t % 3 - 1;
            bool ok = (yy >= 0 && yy < H && xc >= 0 && xc < W);
            v[t] = ok ? xb[c * HW + yy * W + xc] : 0.f;
        }
#pragma unroll
        for (int t = 0; t < 9; t++) {
            const float4* w4 = (const float4*)&ws[(c * 9 + t) * 20];
            float vv = v[t];
#pragma unroll
            for (int q = 0; q < 5; q++) {
                float4 wq = w4[q];
                acc[q].x += vv * wq.x;
                acc[q].y += vv * wq.y;
                acc[q].z += vv * wq.z;
                acc[q].w += vv * wq.w;
            }
        }
    }

    float a[20];
#pragma unroll
    for (int q = 0; q < 5; q++) {
        a[4*q] = acc[q].x; a[4*q+1] = acc[q].y;
        a[4*q+2] = acc[q].z; a[4*q+3] = acc[q].w;
    }
    float* op = g_off + (long)pid * KK;
#pragma unroll
    for (int kk = 0; kk < 18; kk++) op[kk] = a[kk];
}

// ---------------------------------------------------------------------------
// Kernel 4: main. 256 threads, 32 pixels of one row per block.
//  Stage A: bilinear sampling -> smem samp[t][k*64+c] (tap-major, STS.128).
//  Stage B: per-tap SMEM-staged weights; 4o x 2t x 4c register tiling.
// Dynamic smem: samp (32*580*4 = 74240 B) + wbuf (64*64*4 = 16384 B).
// ---------------------------------------------------------------------------
__global__ void __launch_bounds__(256) k_main(float* __restrict__ out) {
    extern __shared__ float smem[];
    float* samp = smem;                 // [TPX][SROW]
    float* wbuf = smem + TPX * SROW;    // [64c][64o]; reused for output staging

    int b   = blockIdx.z;
    int y   = blockIdx.y;
    int x0  = blockIdx.x * TPX;
    int tid = threadIdx.x;

    // ---- Stage A: sampling. thread -> (pixel t, 8 channels)
    {
        int t  = tid >> 3;            // 0..31
        int c0 = (tid & 7) * 8;       // 0,8,...,56
        int xo = x0 + t;
        int pidx = b * HW + y * W + xo;
        const float* op = g_off + (long)pidx * KK;
        float* srow = samp + t * SROW;
#pragma unroll
        for (int k = 0; k < 9; k++) {
            int ky = k / 3, kx = k % 3;
            float py = op[2*k]     + (float)(y  + ky - 1);
            float px = op[2*k + 1] + (float)(xo + kx - 1);
            float fy = floorf(py), fx = floorf(px);
            float wy = py - fy,    wx = px - fx;
            int iy0 = (int)fy, ix0 = (int)fx;
            int iy1 = iy0 + 1, ix1 = ix0 + 1;
            float vy0 = (iy0 >= 0 && iy0 < H) ? 1.f : 0.f;
            float vy1 = (iy1 >= 0 && iy1 < H) ? 1.f : 0.f;
            float vx0 = (ix0 >= 0 && ix0 < W) ? 1.f : 0.f;
            float vx1 = (ix1 >= 0 && ix1 < W) ? 1.f : 0.f;
            float w00 = (1.f - wy) * (1.f - wx) * vy0 * vx0;
            float w01 = (1.f - wy) * wx         * vy0 * vx1;
            float w10 = wy         * (1.f - wx) * vy1 * vx0;
            float w11 = wy         * wx         * vy1 * vx1;
            int cy0 = min(max(iy0, 0), H - 1), cy1 = min(max(iy1, 0), H - 1);
            int cx0 = min(max(ix0, 0), W - 1), cx1 = min(max(ix1, 0), W - 1);
            const float* p00 = g_xt + ((long)(b * HW + cy0 * W + cx0)) * C + c0;
            const float* p01 = g_xt + ((long)(b * HW + cy0 * W + cx1)) * C + c0;
            const float* p10 = g_xt + ((long)(b * HW + cy1 * W + cx0)) * C + c0;
            const float* p11 = g_xt + ((long)(b * HW + cy1 * W + cx1)) * C + c0;
#pragma unroll
            for (int j = 0; j < 2; j++) {
                float4 a00 = *(const float4*)(p00 + 4*j);
                float4 a01 = *(const float4*)(p01 + 4*j);
                float4 a10 = *(const float4*)(p10 + 4*j);
                float4 a11 = *(const float4*)(p11 + 4*j);
                float s0 = w00*a00.x + w01*a01.x + w10*a10.x + w11*a11.x;
                float s1 = w00*a00.y + w01*a01.y + w10*a10.y + w11*a11.y;
                float s2 = w00*a00.z + w01*a01.z + w10*a10.z + w11*a11.z;
                float s3 = w00*a00.w + w01*a01.w + w10*a10.w + w11*a11.w;
                *(float4*)(srow + k * 64 + c0 + 4*j) = make_float4(s0, s1, s2, s3);
            }
        }
    }
    __syncthreads();

    // ---- Stage B: GEMM. thread -> 4 outputs (o0..o0+3) x 2 pixels (t0,t0+1)
    int o0 = (tid & 15) * 4;
    int t0 = (tid >> 4) * 2;          // 0,2,...,30
    float4 acc0 = make_float4(0,0,0,0);
    float4 acc1 = make_float4(0,0,0,0);

    for (int k = 0; k < 9; k++) {
        // Cooperatively stage this tap's 64x64 weight block into smem.
        const float4* wsrc = (const float4*)(g_wkt2 + k * (C * COUT));
        float4* wdst = (float4*)wbuf;
#pragma unroll
        for (int j = 0; j < 4; j++)
            wdst[tid + j * 256] = wsrc[tid + j * 256];
        __syncthreads();

        const float* s0p = samp + t0 * SROW + k * 64;
        const float* s1p = s0p + SROW;
#pragma unroll
        for (int cq = 0; cq < 16; cq++) {
            int c = cq * 4;
            float4 sa = *(const float4*)(s0p + c);
            float4 sb = *(const float4*)(s1p + c);
            float4 w0 = *(const float4*)(wbuf + (c + 0) * COUT + o0);
            float4 w1 = *(const float4*)(wbuf + (c + 1) * COUT + o0);
            float4 w2 = *(const float4*)(wbuf + (c + 2) * COUT + o0);
            float4 w3 = *(const float4*)(wbuf + (c + 3) * COUT + o0);
            fma4(acc0, sa.x, w0); fma4(acc0, sa.y, w1);
            fma4(acc0, sa.z, w2); fma4(acc0, sa.w, w3);
            fma4(acc1, sb.x, w0); fma4(acc1, sb.y, w1);
            fma4(acc1, sb.z, w2); fma4(acc1, sb.w, w3);
        }
        __syncthreads();   // protect wbuf before next tap's overwrite
    }

    // ---- Output: stage through SMEM (reuse wbuf) for coalesced stores
    float* ob = wbuf;                 // [COUT][33]
#pragma unroll
    for (int i = 0; i < 4; i++) {
        ob[(o0 + i) * 33 + t0]     = (&acc0.x)[i];
        ob[(o0 + i) * 33 + t0 + 1] = (&acc1.x)[i];
    }
    __syncthreads();
#pragma unroll
    for (int j = 0; j < 8; j++) {
        int i = tid + j * 256;
        int o = i >> 5;
        int t = i & 31;
        out[((long)(b * COUT + o) * H + y) * W + x0 + t] = ob[o * 33 + t];
    }
}

// ---------------------------------------------------------------------------
extern "C" void kernel_launch(void* const* d_in, const int* in_sizes, int n_in,
                              void* d_out, int out_size) {
    const float* x  = (const float*)d_in[0];
    const float* wp = (const float*)d_in[1];
    const float* bp = (const float*)d_in[2];
    const float* wd = (const float*)d_in[3];
    float* out = (float*)d_out;

    static int smem_set = 0;
    int smem_bytes = (TPX * SROW + C * COUT) * 4;   // 90624
    if (!smem_set) {
        cudaFuncSetAttribute(k_main, cudaFuncAttributeMaxDynamicSharedMemorySize,
                             smem_bytes);
        smem_set = 1;
    }

    k_transpose_x<<<dim3(HW / 32, C / 32, B), dim3(32, 8)>>>(x);
    k_wkt<<<(9 * C * COUT + 255) / 256, 256>>>(wd);
    k_offset<<<(B * HW) / 256, 256>>>(x, wp, bp);
    k_main<<<dim3(W / TPX, H, B), 256, smem_bytes>>>(out);
}

// round 4
// speedup vs baseline: 1.0289x; 1.0015x over previous
#include <cuda_runtime.h>
#include <math.h>

#define B    4
#define C    64
#define H    128
#define W    128
#define COUT 64
#define KK   18       // 2*K offset channels
#define CK   576      // C*9
#define HW   16384    // H*W
#define TPX  32       // pixels per main-kernel block
#define NT   128      // threads in k_main
#define SROW 580      // padded samp row

// Scratch (device globals — no runtime allocation allowed)
__device__ float g_xt[B * HW * C];       // x transposed to [b][y][x][c]
__device__ float g_off[B * HW * KK];     // offsets [b][y][x][18]
__device__ float g_wkt2[9 * C * COUT];   // weights [k][c][o]

__device__ __forceinline__ void fma4(float4& a, float s, const float4& v) {
    a.x += s * v.x; a.y += s * v.y; a.z += s * v.z; a.w += s * v.w;
}

// ---------------------------------------------------------------------------
// Kernel 1: transpose x (B,C,H,W) -> (B,HW,C), SMEM-tiled 32x32
// ---------------------------------------------------------------------------
__global__ void k_transpose_x(const float* __restrict__ x) {
    __shared__ float tile[32][33];
    int b   = blockIdx.z;
    int c0  = blockIdx.y * 32;
    int hw0 = blockIdx.x * 32;
    int tx = threadIdx.x, ty = threadIdx.y;   // 32 x 8
#pragma unroll
    for (int j = 0; j < 4; j++) {
        int c = c0 + ty + j * 8;
        tile[ty + j * 8][tx] = x[(b * C + c) * HW + hw0 + tx];
    }
    __syncthreads();
#pragma unroll
    for (int j = 0; j < 4; j++) {
        int hw = hw0 + ty + j * 8;
        g_xt[(b * HW + hw) * C + c0 + tx] = tile[tx][ty + j * 8];
    }
}

// ---------------------------------------------------------------------------
// Kernel 2: reorder w_d (COUT, C, 3, 3) -> g_wkt2[k][c][o]
// ---------------------------------------------------------------------------
__global__ void k_wkt(const float* __restrict__ wd) {
    int d = blockIdx.x * 256 + threadIdx.x;
    if (d < 9 * C * COUT) {
        int o = d & 63;
        int c = (d >> 6) & 63;
        int k = d >> 12;
        g_wkt2[d] = wd[o * CK + c * 9 + k];
    }
}

// ---------------------------------------------------------------------------
// Kernel 3: offset conv — 3x3, C=64 -> 18, pad 1, + bias.
// ---------------------------------------------------------------------------
__global__ void __launch_bounds__(256) k_offset(const float* __restrict__ x,
                                                const float* __restrict__ wp,
                                                const float* __restrict__ bp) {
    __shared__ float ws[C * 9 * 20];   // 46080 B
    int tid = threadIdx.x;
    for (int i = tid; i < C * 9 * 20; i += 256) {
        int kk = i % 20;
        int ct = i / 20;               // c*9 + tap
        ws[i] = (kk < 18) ? wp[kk * CK + ct] : 0.f;
    }
    __syncthreads();

    int pid = blockIdx.x * 256 + tid;
    int b  = pid >> 14;
    int yx = pid & (HW - 1);
    int y  = yx >> 7;
    int xx = yx & 127;

    float4 acc[5];
    {
        float a[20];
#pragma unroll
        for (int kk = 0; kk < 18; kk++) a[kk] = bp[kk];
        a[18] = 0.f; a[19] = 0.f;
#pragma unroll
        for (int q = 0; q < 5; q++)
            acc[q] = make_float4(a[4*q], a[4*q+1], a[4*q+2], a[4*q+3]);
    }

    const float* xb = x + b * C * HW;
    for (int c = 0; c < C; c++) {
        float v[9];
#pragma unroll
        for (int t = 0; t < 9; t++) {
            int yy = y + t / 3 - 1;
            int xc = xx + t % 3 - 1;
            bool ok = (yy >= 0 && yy < H && xc >= 0 && xc < W);
            v[t] = ok ? xb[c * HW + yy * W + xc] : 0.f;
        }
#pragma unroll
        for (int t = 0; t < 9; t++) {
            const float4* w4 = (const float4*)&ws[(c * 9 + t) * 20];
            float vv = v[t];
#pragma unroll
            for (int q = 0; q < 5; q++) {
                float4 wq = w4[q];
                acc[q].x += vv * wq.x;
                acc[q].y += vv * wq.y;
                acc[q].z += vv * wq.z;
                acc[q].w += vv * wq.w;
            }
        }
    }

    float a[20];
#pragma unroll
    for (int q = 0; q < 5; q++) {
        a[4*q] = acc[q].x; a[4*q+1] = acc[q].y;
        a[4*q+2] = acc[q].z; a[4*q+3] = acc[q].w;
    }
    float* op = g_off + (long)pid * KK;
#pragma unroll
    for (int kk = 0; kk < 18; kk++) op[kk] = a[kk];
}

// ---------------------------------------------------------------------------
// Kernel 4: main. 128 threads, 32 pixels of one row per block.
//  Stage A: bilinear sampling -> smem samp[t][k*64+c] (tap-major, STS.128).
//  Stage B: per-tap double-buffered SMEM weights; 4o x 4t x 4c register
//           tiling -> 16 accumulators, 8 LDS.128 per 64 FFMA.
// Dynamic smem: samp (32*580*4 = 74240 B) + wbuf (2*64*64*4 = 32768 B).
// ---------------------------------------------------------------------------
__global__ void __launch_bounds__(NT) k_main(float* __restrict__ out) {
    extern __shared__ float smem[];
    float* samp = smem;                 // [TPX][SROW]
    float* wbuf = smem + TPX * SROW;    // [2][64c][64o]; reused for out staging

    int b   = blockIdx.z;
    int y   = blockIdx.y;
    int x0  = blockIdx.x * TPX;
    int tid = threadIdx.x;

    // ---- Stage A: sampling. thread -> (pixel t, 16 channels)
    {
        int t  = tid >> 2;            // 0..31
        int c0 = (tid & 3) * 16;      // 0,16,32,48
        int xo = x0 + t;
        int pidx = b * HW + y * W + xo;
        const float* op = g_off + (long)pidx * KK;
        float* srow = samp + t * SROW;
#pragma unroll
        for (int k = 0; k < 9; k++) {
            int ky = k / 3, kx = k % 3;
            float py = op[2*k]     + (float)(y  + ky - 1);
            float px = op[2*k + 1] + (float)(xo + kx - 1);
            float fy = floorf(py), fx = floorf(px);
            float wy = py - fy,    wx = px - fx;
            int iy0 = (int)fy, ix0 = (int)fx;
            int iy1 = iy0 + 1, ix1 = ix0 + 1;
            float vy0 = (iy0 >= 0 && iy0 < H) ? 1.f : 0.f;
            float vy1 = (iy1 >= 0 && iy1 < H) ? 1.f : 0.f;
            float vx0 = (ix0 >= 0 && ix0 < W) ? 1.f : 0.f;
            float vx1 = (ix1 >= 0 && ix1 < W) ? 1.f : 0.f;
            float w00 = (1.f - wy) * (1.f - wx) * vy0 * vx0;
            float w01 = (1.f - wy) * wx         * vy0 * vx1;
            float w10 = wy         * (1.f - wx) * vy1 * vx0;
            float w11 = wy         * wx         * vy1 * vx1;
            int cy0 = min(max(iy0, 0), H - 1), cy1 = min(max(iy1, 0), H - 1);
            int cx0 = min(max(ix0, 0), W - 1), cx1 = min(max(ix1, 0), W - 1);
            const float* p00 = g_xt + ((long)(b * HW + cy0 * W + cx0)) * C + c0;
            const float* p01 = g_xt + ((long)(b * HW + cy0 * W + cx1)) * C + c0;
            const float* p10 = g_xt + ((long)(b * HW + cy1 * W + cx0)) * C + c0;
            const float* p11 = g_xt + ((long)(b * HW + cy1 * W + cx1)) * C + c0;
#pragma unroll
            for (int j = 0; j < 4; j++) {
                float4 a00 = *(const float4*)(p00 + 4*j);
                float4 a01 = *(const float4*)(p01 + 4*j);
                float4 a10 = *(const float4*)(p10 + 4*j);
                float4 a11 = *(const float4*)(p11 + 4*j);
                float s0 = w00*a00.x + w01*a01.x + w10*a10.x + w11*a11.x;
                float s1 = w00*a00.y + w01*a01.y + w10*a10.y + w11*a11.y;
                float s2 = w00*a00.z + w01*a01.z + w10*a10.z + w11*a11.z;
                float s3 = w00*a00.w + w01*a01.w + w10*a10.w + w11*a11.w;
                *(float4*)(srow + k * 64 + c0 + 4*j) = make_float4(s0, s1, s2, s3);
            }
        }
    }

    // Preload tap-0 weights into buffer 0 (overlaps with other threads' sampling)
    {
        const float4* wsrc = (const float4*)g_wkt2;
        float4* wdst = (float4*)wbuf;
#pragma unroll
        for (int j = 0; j < 8; j++)
            wdst[tid + j * NT] = wsrc[tid + j * NT];
    }
    __syncthreads();

    // ---- Stage B: GEMM. thread -> 4 outputs (o0..o0+3) x 4 pixels (t0..t0+3)
    int o0 = (tid & 15) * 4;
    int t0 = (tid >> 4) * 4;          // 0,4,...,28
    float4 acc[4];
#pragma unroll
    for (int i = 0; i < 4; i++) acc[i] = make_float4(0, 0, 0, 0);

    const float* s0p = samp + (t0 + 0) * SROW;
    const float* s1p = samp + (t0 + 1) * SROW;
    const float* s2p = samp + (t0 + 2) * SROW;
    const float* s3p = samp + (t0 + 3) * SROW;

#pragma unroll
    for (int k = 0; k < 9; k++) {
        // prefetch next tap's weights into the other buffer
        if (k < 8) {
            const float4* wsrc = (const float4*)(g_wkt2 + (k + 1) * (C * COUT));
            float4* wdst = (float4*)(wbuf + ((k + 1) & 1) * (C * COUT));
#pragma unroll
            for (int j = 0; j < 8; j++)
                wdst[tid + j * NT] = wsrc[tid + j * NT];
        }
        const float* wb = wbuf + (k & 1) * (C * COUT);
        int kb = k * 64;
#pragma unroll 4
        for (int cq = 0; cq < 16; cq++) {
            int c = cq * 4;
            float4 sa = *(const float4*)(s0p + kb + c);
            float4 sb = *(const float4*)(s1p + kb + c);
            float4 sc = *(const float4*)(s2p + kb + c);
            float4 sd = *(const float4*)(s3p + kb + c);
            float4 w0 = *(const float4*)(wb + (c + 0) * COUT + o0);
            float4 w1 = *(const float4*)(wb + (c + 1) * COUT + o0);
            float4 w2 = *(const float4*)(wb + (c + 2) * COUT + o0);
            float4 w3 = *(const float4*)(wb + (c + 3) * COUT + o0);
            fma4(acc[0], sa.x, w0); fma4(acc[0], sa.y, w1);
            fma4(acc[0], sa.z, w2); fma4(acc[0], sa.w, w3);
            fma4(acc[1], sb.x, w0); fma4(acc[1], sb.y, w1);
            fma4(acc[1], sb.z, w2); fma4(acc[1], sb.w, w3);
            fma4(acc[2], sc.x, w0); fma4(acc[2], sc.y, w1);
            fma4(acc[2], sc.z, w2); fma4(acc[2], sc.w, w3);
            fma4(acc[3], sd.x, w0); fma4(acc[3], sd.y, w1);
            fma4(acc[3], sd.z, w2); fma4(acc[3], sd.w, w3);
        }
        __syncthreads();   // next-tap weights ready / safe to overwrite k-1 buf
    }

    // ---- Output: stage through SMEM (reuse wbuf) for coalesced stores
    float* ob = wbuf;                 // [COUT][33]
#pragma unroll
    for (int i = 0; i < 4; i++)
#pragma unroll
        for (int j = 0; j < 4; j++)
            ob[(o0 + i) * 33 + t0 + j] = (&acc[j].x)[i];
    __syncthreads();
#pragma unroll
    for (int j = 0; j < 16; j++) {
        int i = tid + j * NT;
        int o = i >> 5;
        int t = i & 31;
        out[((long)(b * COUT + o) * H + y) * W + x0 + t] = ob[o * 33 + t];
    }
}

// ---------------------------------------------------------------------------
extern "C" void kernel_launch(void* const* d_in, const int* in_sizes, int n_in,
                              void* d_out, int out_size) {
    const float* x  = (const float*)d_in[0];
    const float* wp = (const float*)d_in[1];
    const float* bp = (const float*)d_in[2];
    const float* wd = (const float*)d_in[3];
    float* out = (float*)d_out;

    static int smem_set = 0;
    int smem_bytes = (TPX * SROW + 2 * C * COUT) * 4;   // 107008
    if (!smem_set) {
        cudaFuncSetAttribute(k_main, cudaFuncAttributeMaxDynamicSharedMemorySize,
                             smem_bytes);
        smem_set = 1;
    }

    k_transpose_x<<<dim3(HW / 32, C / 32, B), dim3(32, 8)>>>(x);
    k_wkt<<<(9 * C * COUT + 255) / 256, 256>>>(wd);
    k_offset<<<(B * HW) / 256, 256>>>(x, wp, bp);
    k_main<<<dim3(W / TPX, H, B), NT, smem_bytes>>>(out);
}